// round 1
// baseline (speedup 1.0000x reference)
#include <cuda_runtime.h>
#include <cstdint>

#define B 8
#define C 256
#define N 3136
#define NQ (N/4)
#define NC 50
#define TILE 128
#define KT 16

// ---------------- scratch (static device globals: allocation-guard safe) ----
__device__ float    g_d2[(size_t)B * N * N];   // clamped squared distances (raw, before /C)
__device__ float    g_sq[B * N];
__device__ float    g_dens[B * N];
__device__ float    g_score[B * N];
__device__ unsigned g_maxb[B];
__device__ int      g_idx[B * NC];

// ---------------- threefry-2x32 (JAX-compatible) ---------------------------
__device__ __forceinline__ uint32_t rotl32(uint32_t x, int r) {
    return (x << r) | (x >> (32 - r));
}

__device__ __forceinline__ void threefry2x32_k42(uint32_t x0, uint32_t x1,
                                                 uint32_t& o0, uint32_t& o1) {
    const uint32_t ks0 = 0u;
    const uint32_t ks1 = 42u;
    const uint32_t ks2 = 0x1BD11BDAu ^ 42u;
    x0 += ks0; x1 += ks1;
#define TF_RND(r) { x0 += x1; x1 = rotl32(x1, r); x1 ^= x0; }
    TF_RND(13) TF_RND(15) TF_RND(26) TF_RND(6)
    x0 += ks1; x1 += ks2 + 1u;
    TF_RND(17) TF_RND(29) TF_RND(16) TF_RND(24)
    x0 += ks2; x1 += ks0 + 2u;
    TF_RND(13) TF_RND(15) TF_RND(26) TF_RND(6)
    x0 += ks0; x1 += ks1 + 3u;
    TF_RND(17) TF_RND(29) TF_RND(16) TF_RND(24)
    x0 += ks1; x1 += ks2 + 4u;
    TF_RND(13) TF_RND(15) TF_RND(26) TF_RND(6)
    x0 += ks2; x1 += ks0 + 5u;
#undef TF_RND
    o0 = x0; o1 = x1;
}

// uniform [0,1) noise for flat index g over shape [B,N] (count = 25088, half = 12544)
__device__ __forceinline__ float jax_uniform_noise(int g) {
    const int half = (B * N) / 2;  // 12544
    uint32_t lane = (g < half) ? (uint32_t)g : (uint32_t)(g - half);
    uint32_t o0, o1;
    threefry2x32_k42(lane, lane + (uint32_t)half, o0, o1);
    uint32_t bits = (g < half) ? o0 : o1;
    float f = __uint_as_float((bits >> 9) | 0x3F800000u) - 1.0f;
    return f;
}

// ---------------- kernels ---------------------------------------------------
__global__ void init_kernel() {
    int t = threadIdx.x;
    if (t < B) g_maxb[t] = 0u;
}

__global__ void sq_kernel(const float* __restrict__ x) {
    int g = blockIdx.x * blockDim.x + threadIdx.x;
    if (g >= B * N) return;
    int b = g / N, n = g % N;
    const float* p = x + (size_t)b * C * N + n;
    float s = 0.f;
#pragma unroll 8
    for (int c = 0; c < C; c++) {
        float v = p[(size_t)c * N];
        s = fmaf(v, v, s);
    }
    g_sq[g] = s;
}

// 128x128 tile SGEMM-like Gram: d2[i][j] = max(sq_i + sq_j - 2*dot(x_i,x_j), 0)
__global__ __launch_bounds__(256, 2) void gram_kernel(const float* __restrict__ x) {
    const int b  = blockIdx.z;
    const int i0 = blockIdx.y * TILE;
    const int j0 = blockIdx.x * TILE;
    const float* X = x + (size_t)b * C * N;

    __shared__ float As[KT][TILE];
    __shared__ float Bs[KT][TILE];

    const int tid = threadIdx.x;
    const int tx = tid & 15;   // 16 threads over j
    const int ty = tid >> 4;   // 16 threads over i

    float acc[8][8];
#pragma unroll
    for (int r = 0; r < 8; r++)
#pragma unroll
        for (int c = 0; c < 8; c++) acc[r][c] = 0.f;

    for (int k0 = 0; k0 < C; k0 += KT) {
#pragma unroll
        for (int s = 0; s < 2; s++) {
            int slot = tid + 256 * s;      // 0..511 float4 slots
            int kk = slot >> 5;            // 32 float4 per 128-wide row
            int f4 = slot & 31;
            float4 va = make_float4(0.f, 0.f, 0.f, 0.f);
            int icol = i0 + f4 * 4;
            if (icol < N)
                va = *reinterpret_cast<const float4*>(&X[(size_t)(k0 + kk) * N + icol]);
            *reinterpret_cast<float4*>(&As[kk][f4 * 4]) = va;
            float4 vb = make_float4(0.f, 0.f, 0.f, 0.f);
            int jcol = j0 + f4 * 4;
            if (jcol < N)
                vb = *reinterpret_cast<const float4*>(&X[(size_t)(k0 + kk) * N + jcol]);
            *reinterpret_cast<float4*>(&Bs[kk][f4 * 4]) = vb;
        }
        __syncthreads();
#pragma unroll
        for (int kk = 0; kk < KT; kk++) {
            float a[8], bb[8];
            *reinterpret_cast<float4*>(&a[0])  = *reinterpret_cast<float4*>(&As[kk][ty * 8]);
            *reinterpret_cast<float4*>(&a[4])  = *reinterpret_cast<float4*>(&As[kk][ty * 8 + 4]);
            *reinterpret_cast<float4*>(&bb[0]) = *reinterpret_cast<float4*>(&Bs[kk][tx * 8]);
            *reinterpret_cast<float4*>(&bb[4]) = *reinterpret_cast<float4*>(&Bs[kk][tx * 8 + 4]);
#pragma unroll
            for (int r = 0; r < 8; r++)
#pragma unroll
                for (int c = 0; c < 8; c++)
                    acc[r][c] = fmaf(a[r], bb[c], acc[r][c]);
        }
        __syncthreads();
    }

    // epilogue: d2 = max(sq_i + sq_j - 2*acc, 0), store + per-batch max
    float sqi[8], sqj[8];
    const int jb = j0 + tx * 8;
    const bool jok = (jb < N);   // N%8==0 -> whole 8-group in or out
#pragma unroll
    for (int r = 0; r < 8; r++) {
        int gi = i0 + ty * 8 + r;
        sqi[r] = (gi < N) ? g_sq[b * N + gi] : 0.f;
    }
#pragma unroll
    for (int c = 0; c < 8; c++) {
        int gj = jb + c;
        sqj[c] = (gj < N) ? g_sq[b * N + gj] : 0.f;
    }
    float tmax = 0.f;
#pragma unroll
    for (int r = 0; r < 8; r++) {
        int gi = i0 + ty * 8 + r;
        if (gi < N && jok) {
            float vals[8];
#pragma unroll
            for (int c = 0; c < 8; c++) {
                float d2 = fmaxf(sqi[r] + sqj[c] - 2.f * acc[r][c], 0.f);
                vals[c] = d2;
                tmax = fmaxf(tmax, d2);
            }
            float* dst = &g_d2[((size_t)b * N + gi) * N + jb];
            *reinterpret_cast<float4*>(dst)     = *reinterpret_cast<float4*>(&vals[0]);
            *reinterpret_cast<float4*>(dst + 4) = *reinterpret_cast<float4*>(&vals[4]);
        }
    }

    // block max -> one atomic per block
    __shared__ float red[256];
    red[tid] = tmax;
    __syncthreads();
    for (int o = 128; o > 0; o >>= 1) {
        if (tid < o) red[tid] = fmaxf(red[tid], red[tid + o]);
        __syncthreads();
    }
    if (tid == 0) atomicMax(&g_maxb[b], __float_as_uint(red[0]));
}

__device__ __forceinline__ void ins5(float* best, float v) {
    if (v < best[4]) {
        int p = 4;
#pragma unroll
        for (int t = 0; t < 4; t++) {
            if (p > 0 && v < best[p - 1]) { best[p] = best[p - 1]; p--; }
        }
        best[p] = v;
    }
}

// 5-NN density + threefry noise (one thread per row)
__global__ void knn_kernel() {
    int g = blockIdx.x * blockDim.x + threadIdx.x;
    if (g >= B * N) return;
    const float4* row = reinterpret_cast<const float4*>(&g_d2[(size_t)g * N]);
    float best[5] = {3.4e38f, 3.4e38f, 3.4e38f, 3.4e38f, 3.4e38f};
    for (int q = 0; q < NQ; q++) {
        float4 v = row[q];
        ins5(best, v.x); ins5(best, v.y); ins5(best, v.z); ins5(best, v.w);
    }
    // mimic jax: dist = sqrt(d2)/sqrt(C); density = exp(-mean(dist^2))
    float s = 0.f;
#pragma unroll
    for (int t = 0; t < 5; t++) {
        float d = sqrtf(best[t]) / 16.0f;
        s = s + d * d;
    }
    float dens = expf(-(s / 5.0f));
    g_dens[g] = dens + jax_uniform_noise(g) * 1e-6f;
}

// dist_parent + score (one thread per row)
__global__ void parent_kernel() {
    int g = blockIdx.x * blockDim.x + threadIdx.x;
    if (g >= B * N) return;
    int b = g / N;
    float di = g_dens[g];
    const float4* row = reinterpret_cast<const float4*>(&g_d2[(size_t)g * N]);
    const float4* dr  = reinterpret_cast<const float4*>(&g_dens[(size_t)b * N]);
    float mn = 3.4e38f;
    for (int q = 0; q < NQ; q++) {
        float4 v = row[q];
        float4 dd = dr[q];
        if (dd.x > di) mn = fminf(mn, v.x);
        if (dd.y > di) mn = fminf(mn, v.y);
        if (dd.z > di) mn = fminf(mn, v.z);
        if (dd.w > di) mn = fminf(mn, v.w);
    }
    float dmax = sqrtf(__uint_as_float(g_maxb[b])) / 16.0f;
    float dp = fminf(dmax, sqrtf(mn) / 16.0f);
    g_score[g] = dp * di;
}

// per-batch top-50, jax top_k tie-break (lower index wins on equal score)
__global__ void topk_kernel() {
    int b = blockIdx.x;
    __shared__ float s[N];
    __shared__ float rs[256];
    __shared__ int   ri[256];
    int t = threadIdx.x;
    for (int i = t; i < N; i += 256) s[i] = g_score[b * N + i];
    __syncthreads();
    for (int m = 0; m < NC; m++) {
        float bs = -3.4e38f;
        int   bi = N;
        for (int i = t; i < N; i += 256) {
            float v = s[i];
            if (v > bs || (v == bs && i < bi)) { bs = v; bi = i; }
        }
        rs[t] = bs; ri[t] = bi;
        __syncthreads();
        for (int o = 128; o > 0; o >>= 1) {
            if (t < o) {
                if (rs[t + o] > rs[t] || (rs[t + o] == rs[t] && ri[t + o] < ri[t])) {
                    rs[t] = rs[t + o]; ri[t] = ri[t + o];
                }
            }
            __syncthreads();
        }
        if (t == 0) {
            g_idx[b * NC + m] = ri[0];
            s[ri[0]] = -3.4e38f;
        }
        __syncthreads();
    }
}

__global__ void gather_kernel(const float* __restrict__ x, float* __restrict__ out) {
    int g = blockIdx.x * blockDim.x + threadIdx.x;
    if (g >= B * C * NC) return;
    int m = g % NC;
    int c = (g / NC) % C;
    int b = g / (NC * C);
    int idx = g_idx[b * NC + m];
    out[g] = x[(size_t)b * C * N + (size_t)c * N + idx];
}

// ---------------- launch -----------------------------------------------------
extern "C" void kernel_launch(void* const* d_in, const int* in_sizes, int n_in,
                              void* d_out, int out_size) {
    const float* x = (const float*)d_in[0];
    float* out = (float*)d_out;

    init_kernel<<<1, 32>>>();
    sq_kernel<<<(B * N + 255) / 256, 256>>>(x);
    dim3 gg((N + TILE - 1) / TILE, (N + TILE - 1) / TILE, B);
    gram_kernel<<<gg, 256>>>(x);
    knn_kernel<<<(B * N + 255) / 256, 256>>>();
    parent_kernel<<<(B * N + 255) / 256, 256>>>();
    topk_kernel<<<B, 256>>>();
    gather_kernel<<<(B * C * NC + 255) / 256, 256>>>(x, out);
}

// round 2
// speedup vs baseline: 1.7131x; 1.7131x over previous
#include <cuda_runtime.h>
#include <cstdint>

#define B 8
#define C 256
#define N 3136
#define NQ (N/4)
#define NC 50
#define TILE 128
#define KT 16
#define NT 25              // ceil(N/128)
#define NPAIRS (NT*(NT+1)/2)   // 325 upper-triangle tile pairs

// ---------------- scratch (static device globals: allocation-guard safe) ----
__device__ float    g_d2[(size_t)B * N * N];   // clamped squared distances (raw, before /C)
__device__ float    g_sq[B * N];
__device__ float    g_dens[B * N];
__device__ float    g_score[B * N];
__device__ unsigned g_maxb[B];
__device__ int      g_idx[B * NC];

// ---------------- threefry-2x32 (JAX-compatible) ---------------------------
__device__ __forceinline__ uint32_t rotl32(uint32_t x, int r) {
    return (x << r) | (x >> (32 - r));
}

__device__ __forceinline__ void threefry2x32_k42(uint32_t x0, uint32_t x1,
                                                 uint32_t& o0, uint32_t& o1) {
    const uint32_t ks0 = 0u;
    const uint32_t ks1 = 42u;
    const uint32_t ks2 = 0x1BD11BDAu ^ 42u;
    x0 += ks0; x1 += ks1;
#define TF_RND(r) { x0 += x1; x1 = rotl32(x1, r); x1 ^= x0; }
    TF_RND(13) TF_RND(15) TF_RND(26) TF_RND(6)
    x0 += ks1; x1 += ks2 + 1u;
    TF_RND(17) TF_RND(29) TF_RND(16) TF_RND(24)
    x0 += ks2; x1 += ks0 + 2u;
    TF_RND(13) TF_RND(15) TF_RND(26) TF_RND(6)
    x0 += ks0; x1 += ks1 + 3u;
    TF_RND(17) TF_RND(29) TF_RND(16) TF_RND(24)
    x0 += ks1; x1 += ks2 + 4u;
    TF_RND(13) TF_RND(15) TF_RND(26) TF_RND(6)
    x0 += ks2; x1 += ks0 + 5u;
#undef TF_RND
    o0 = x0; o1 = x1;
}

__device__ __forceinline__ float jax_uniform_noise(int g) {
    const int half = (B * N) / 2;  // 12544
    uint32_t lane = (g < half) ? (uint32_t)g : (uint32_t)(g - half);
    uint32_t o0, o1;
    threefry2x32_k42(lane, lane + (uint32_t)half, o0, o1);
    uint32_t bits = (g < half) ? o0 : o1;
    return __uint_as_float((bits >> 9) | 0x3F800000u) - 1.0f;
}

// ---------------- kernels ---------------------------------------------------
__global__ void init_kernel() {
    int t = threadIdx.x;
    if (t < B) g_maxb[t] = 0u;
}

__global__ void sq_kernel(const float* __restrict__ x) {
    int g = blockIdx.x * blockDim.x + threadIdx.x;
    if (g >= B * N) return;
    int b = g / N, n = g % N;
    const float* p = x + (size_t)b * C * N + n;
    float s = 0.f;
#pragma unroll 8
    for (int c = 0; c < C; c++) {
        float v = p[(size_t)c * N];
        s = fmaf(v, v, s);
    }
    g_sq[g] = s;
}

// Symmetric Gram: only upper-triangle 128x128 tile pairs; mirror-write via smem transpose.
__global__ __launch_bounds__(256, 2) void gram_kernel(const float* __restrict__ x) {
    const int b = blockIdx.z;

    // decode upper-triangle pair index -> (ti, tj), tj >= ti
    int rem = blockIdx.x;
    int ti = 0;
    while (rem >= NT - ti) { rem -= NT - ti; ti++; }
    const int tj = ti + rem;
    const int i0 = ti * TILE;
    const int j0 = tj * TILE;

    const float* X = x + (size_t)b * C * N;

    __shared__ float As[KT][TILE];
    __shared__ float Bs[KT][TILE];
    __shared__ float Ts[16][129];      // transpose staging (padded)
    __shared__ float red[256];

    const int tid = threadIdx.x;
    const int tx = tid & 15;   // 16 threads over j
    const int ty = tid >> 4;   // 16 threads over i

    float acc[8][8];
#pragma unroll
    for (int r = 0; r < 8; r++)
#pragma unroll
        for (int c = 0; c < 8; c++) acc[r][c] = 0.f;

    for (int k0 = 0; k0 < C; k0 += KT) {
#pragma unroll
        for (int s = 0; s < 2; s++) {
            int slot = tid + 256 * s;      // 0..511 float4 slots
            int kk = slot >> 5;            // 32 float4 per 128-wide row
            int f4 = slot & 31;
            float4 va = make_float4(0.f, 0.f, 0.f, 0.f);
            int icol = i0 + f4 * 4;
            if (icol < N)
                va = *reinterpret_cast<const float4*>(&X[(size_t)(k0 + kk) * N + icol]);
            *reinterpret_cast<float4*>(&As[kk][f4 * 4]) = va;
            float4 vb = make_float4(0.f, 0.f, 0.f, 0.f);
            int jcol = j0 + f4 * 4;
            if (jcol < N)
                vb = *reinterpret_cast<const float4*>(&X[(size_t)(k0 + kk) * N + jcol]);
            *reinterpret_cast<float4*>(&Bs[kk][f4 * 4]) = vb;
        }
        __syncthreads();
#pragma unroll
        for (int kk = 0; kk < KT; kk++) {
            float a[8], bb[8];
            *reinterpret_cast<float4*>(&a[0])  = *reinterpret_cast<float4*>(&As[kk][ty * 8]);
            *reinterpret_cast<float4*>(&a[4])  = *reinterpret_cast<float4*>(&As[kk][ty * 8 + 4]);
            *reinterpret_cast<float4*>(&bb[0]) = *reinterpret_cast<float4*>(&Bs[kk][tx * 8]);
            *reinterpret_cast<float4*>(&bb[4]) = *reinterpret_cast<float4*>(&Bs[kk][tx * 8 + 4]);
#pragma unroll
            for (int r = 0; r < 8; r++)
#pragma unroll
                for (int c = 0; c < 8; c++)
                    acc[r][c] = fmaf(a[r], bb[c], acc[r][c]);
        }
        __syncthreads();
    }

    // epilogue: acc <- d2 = max(sq_i + sq_j - 2*acc, 0); normal write + per-batch max
    float sqi[8], sqj[8];
    const int jb = j0 + tx * 8;
    const bool jok = (jb < N);
#pragma unroll
    for (int r = 0; r < 8; r++) {
        int gi = i0 + ty * 8 + r;
        sqi[r] = (gi < N) ? g_sq[b * N + gi] : 0.f;
    }
#pragma unroll
    for (int c = 0; c < 8; c++) {
        int gj = jb + c;
        sqj[c] = (gj < N) ? g_sq[b * N + gj] : 0.f;
    }
    float tmax = 0.f;
#pragma unroll
    for (int r = 0; r < 8; r++) {
#pragma unroll
        for (int c = 0; c < 8; c++)
            acc[r][c] = fmaxf(sqi[r] + sqj[c] - 2.f * acc[r][c], 0.f);
        int gi = i0 + ty * 8 + r;
        if (gi < N && jok) {
#pragma unroll
            for (int c = 0; c < 8; c++) tmax = fmaxf(tmax, acc[r][c]);
            float* dst = &g_d2[((size_t)b * N + gi) * N + jb];
            *reinterpret_cast<float4*>(dst)     = *reinterpret_cast<float4*>(&acc[r][0]);
            *reinterpret_cast<float4*>(dst + 4) = *reinterpret_cast<float4*>(&acc[r][4]);
        }
    }

    // block max -> one atomic per block
    red[tid] = tmax;
    __syncthreads();
    for (int o = 128; o > 0; o >>= 1) {
        if (tid < o) red[tid] = fmaxf(red[tid], red[tid + o]);
        __syncthreads();
    }
    if (tid == 0) atomicMax(&g_maxb[b], __float_as_uint(red[0]));

    // mirror write for off-diagonal tiles: region rows=j0.., cols=i0.. (coalesced via smem)
    if (ti != tj) {
        for (int s = 0; s < 8; s++) {   // 8 chunks of 16 j-rows
            __syncthreads();
            if ((tx >> 1) == s) {
#pragma unroll
                for (int c = 0; c < 8; c++)
#pragma unroll
                    for (int r = 0; r < 8; r++)
                        Ts[(tx & 1) * 8 + c][ty * 8 + r] = acc[r][c];
            }
            __syncthreads();
#pragma unroll
            for (int w = 0; w < 2; w++) {
                int slot = tid + 256 * w;     // 512 float4 slots = 16 rows x 32 float4
                int jr = slot >> 5;
                int f4 = slot & 31;
                int gj = j0 + s * 16 + jr;
                int gi = i0 + f4 * 4;
                if (gj < N && gi < N) {
                    float4 v = make_float4(Ts[jr][f4 * 4], Ts[jr][f4 * 4 + 1],
                                           Ts[jr][f4 * 4 + 2], Ts[jr][f4 * 4 + 3]);
                    *reinterpret_cast<float4*>(&g_d2[((size_t)b * N + gj) * N + gi]) = v;
                }
            }
        }
    }
}

__device__ __forceinline__ void ins5(float* best, float v) {
    if (v < best[4]) {
        int p = 4;
#pragma unroll
        for (int t = 0; t < 4; t++) {
            if (p > 0 && v < best[p - 1]) { best[p] = best[p - 1]; p--; }
        }
        best[p] = v;
    }
}

// 5-NN density + threefry noise — one WARP per row (coalesced)
__global__ void knn_kernel() {
    int w = (blockIdx.x * blockDim.x + threadIdx.x) >> 5;
    int lane = threadIdx.x & 31;
    if (w >= B * N) return;
    const float4* row = reinterpret_cast<const float4*>(&g_d2[(size_t)w * N]);
    float best[5] = {3.4e38f, 3.4e38f, 3.4e38f, 3.4e38f, 3.4e38f};
    for (int q = lane; q < NQ; q += 32) {
        float4 v = row[q];
        ins5(best, v.x); ins5(best, v.y); ins5(best, v.z); ins5(best, v.w);
    }
    // warp merge: consume 5 global minima in ascending order (same sum order as scalar)
    int ptr = 0;
    float s = 0.f;
#pragma unroll
    for (int t = 0; t < 5; t++) {
        float v = (ptr < 5) ? best[ptr] : 3.4e38f;
        float m = v;
#pragma unroll
        for (int o = 16; o > 0; o >>= 1) m = fminf(m, __shfl_xor_sync(0xffffffffu, m, o));
        unsigned bal = __ballot_sync(0xffffffffu, v == m);
        if (lane == (__ffs(bal) - 1)) ptr++;
        float d = sqrtf(m) / 16.0f;
        s = s + d * d;
    }
    if (lane == 0)
        g_dens[w] = expf(-(s / 5.0f)) + jax_uniform_noise(w) * 1e-6f;
}

// dist_parent + score — one WARP per row (coalesced)
__global__ void parent_kernel() {
    int w = (blockIdx.x * blockDim.x + threadIdx.x) >> 5;
    int lane = threadIdx.x & 31;
    if (w >= B * N) return;
    int b = w / N;
    float di = g_dens[w];
    const float4* row = reinterpret_cast<const float4*>(&g_d2[(size_t)w * N]);
    const float4* dr  = reinterpret_cast<const float4*>(&g_dens[(size_t)b * N]);
    float mn = 3.4e38f;
    for (int q = lane; q < NQ; q += 32) {
        float4 v = row[q];
        float4 dd = dr[q];
        if (dd.x > di) mn = fminf(mn, v.x);
        if (dd.y > di) mn = fminf(mn, v.y);
        if (dd.z > di) mn = fminf(mn, v.z);
        if (dd.w > di) mn = fminf(mn, v.w);
    }
#pragma unroll
    for (int o = 16; o > 0; o >>= 1) mn = fminf(mn, __shfl_xor_sync(0xffffffffu, mn, o));
    if (lane == 0) {
        float dmax = sqrtf(__uint_as_float(g_maxb[b])) / 16.0f;
        float dp = fminf(dmax, sqrtf(mn) / 16.0f);
        g_score[w] = dp * di;
    }
}

// per-batch top-50, jax top_k tie-break (lower index wins on equal score)
__global__ void topk_kernel() {
    int b = blockIdx.x;
    __shared__ float s[N];
    __shared__ float rs[256];
    __shared__ int   ri[256];
    int t = threadIdx.x;
    for (int i = t; i < N; i += 256) s[i] = g_score[b * N + i];
    __syncthreads();
    for (int m = 0; m < NC; m++) {
        float bs = -3.4e38f;
        int   bi = N;
        for (int i = t; i < N; i += 256) {
            float v = s[i];
            if (v > bs || (v == bs && i < bi)) { bs = v; bi = i; }
        }
        rs[t] = bs; ri[t] = bi;
        __syncthreads();
        for (int o = 128; o > 0; o >>= 1) {
            if (t < o) {
                if (rs[t + o] > rs[t] || (rs[t + o] == rs[t] && ri[t + o] < ri[t])) {
                    rs[t] = rs[t + o]; ri[t] = ri[t + o];
                }
            }
            __syncthreads();
        }
        if (t == 0) {
            g_idx[b * NC + m] = ri[0];
            s[ri[0]] = -3.4e38f;
        }
        __syncthreads();
    }
}

__global__ void gather_kernel(const float* __restrict__ x, float* __restrict__ out) {
    int g = blockIdx.x * blockDim.x + threadIdx.x;
    if (g >= B * C * NC) return;
    int m = g % NC;
    int c = (g / NC) % C;
    int b = g / (NC * C);
    int idx = g_idx[b * NC + m];
    out[g] = x[(size_t)b * C * N + (size_t)c * N + idx];
}

// ---------------- launch -----------------------------------------------------
extern "C" void kernel_launch(void* const* d_in, const int* in_sizes, int n_in,
                              void* d_out, int out_size) {
    const float* x = (const float*)d_in[0];
    float* out = (float*)d_out;

    init_kernel<<<1, 32>>>();
    sq_kernel<<<(B * N + 255) / 256, 256>>>(x);
    dim3 gg(NPAIRS, 1, B);
    gram_kernel<<<gg, 256>>>(x);
    int rows = B * N;                        // one warp per row
    knn_kernel<<<(rows * 32 + 255) / 256, 256>>>();
    parent_kernel<<<(rows * 32 + 255) / 256, 256>>>();
    topk_kernel<<<B, 256>>>();
    gather_kernel<<<(B * C * NC + 255) / 256, 256>>>(x, out);
}

// round 3
// speedup vs baseline: 2.1172x; 1.2359x over previous
#include <cuda_runtime.h>
#include <cstdint>

#define B 8
#define C 256
#define N 3136
#define NQ (N/4)
#define NC 50
#define TILE 128
#define KT 16
#define NT 25              // ceil(N/128)
#define NPAIRS (NT*(NT+1)/2)   // 325 upper-triangle tile pairs

// ---------------- scratch (static device globals: allocation-guard safe) ----
__device__ float    g_d2[(size_t)B * N * N];   // clamped squared distances (raw, before /C)
__device__ float    g_sq[B * N];
__device__ float    g_dens[B * N];
__device__ float    g_score[B * N];
__device__ unsigned g_maxb[B];
__device__ int      g_idx[B * NC];

// ---------------- threefry-2x32 (JAX-compatible) ---------------------------
__device__ __forceinline__ uint32_t rotl32(uint32_t x, int r) {
    return (x << r) | (x >> (32 - r));
}

__device__ __forceinline__ void threefry2x32_k42(uint32_t x0, uint32_t x1,
                                                 uint32_t& o0, uint32_t& o1) {
    const uint32_t ks0 = 0u;
    const uint32_t ks1 = 42u;
    const uint32_t ks2 = 0x1BD11BDAu ^ 42u;
    x0 += ks0; x1 += ks1;
#define TF_RND(r) { x0 += x1; x1 = rotl32(x1, r); x1 ^= x0; }
    TF_RND(13) TF_RND(15) TF_RND(26) TF_RND(6)
    x0 += ks1; x1 += ks2 + 1u;
    TF_RND(17) TF_RND(29) TF_RND(16) TF_RND(24)
    x0 += ks2; x1 += ks0 + 2u;
    TF_RND(13) TF_RND(15) TF_RND(26) TF_RND(6)
    x0 += ks0; x1 += ks1 + 3u;
    TF_RND(17) TF_RND(29) TF_RND(16) TF_RND(24)
    x0 += ks1; x1 += ks2 + 4u;
    TF_RND(13) TF_RND(15) TF_RND(26) TF_RND(6)
    x0 += ks2; x1 += ks0 + 5u;
#undef TF_RND
    o0 = x0; o1 = x1;
}

__device__ __forceinline__ float jax_uniform_noise(int g) {
    const int half = (B * N) / 2;  // 12544
    uint32_t lane = (g < half) ? (uint32_t)g : (uint32_t)(g - half);
    uint32_t o0, o1;
    threefry2x32_k42(lane, lane + (uint32_t)half, o0, o1);
    uint32_t bits = (g < half) ? o0 : o1;
    return __uint_as_float((bits >> 9) | 0x3F800000u) - 1.0f;
}

// ---------------- kernels ---------------------------------------------------
__global__ void init_kernel() {
    int t = threadIdx.x;
    if (t < B) g_maxb[t] = 0u;
}

__global__ void sq_kernel(const float* __restrict__ x) {
    int g = blockIdx.x * blockDim.x + threadIdx.x;
    if (g >= B * N) return;
    int b = g / N, n = g % N;
    const float* p = x + (size_t)b * C * N + n;
    float s = 0.f;
#pragma unroll 8
    for (int c = 0; c < C; c++) {
        float v = p[(size_t)c * N];
        s = fmaf(v, v, s);
    }
    g_sq[g] = s;
}

// Symmetric Gram: upper-triangle 128x128 tile pairs; double-buffered mainloop;
// mirror-write via smem transpose.
__global__ __launch_bounds__(256, 2) void gram_kernel(const float* __restrict__ x) {
    const int b = blockIdx.z;

    // decode upper-triangle pair index -> (ti, tj), tj >= ti
    int rem = blockIdx.x;
    int ti = 0;
    while (rem >= NT - ti) { rem -= NT - ti; ti++; }
    const int tj = ti + rem;
    const int i0 = ti * TILE;
    const int j0 = tj * TILE;

    const float* X = x + (size_t)b * C * N;

    __shared__ float As[2][KT][TILE];
    __shared__ float Bs[2][KT][TILE];
    __shared__ float Ts[16][129];      // transpose staging (padded)
    __shared__ float red[256];

    const int tid = threadIdx.x;
    const int tx = tid & 15;   // 16 threads over j
    const int ty = tid >> 4;   // 16 threads over i

    // per-thread load slots (2 float4 per array per K-step)
    const int kk0 = tid >> 5;            // slot s=0
    const int kk1 = (tid + 256) >> 5;    // slot s=1
    const int f4  = tid & 31;
    const int icol = i0 + f4 * 4;
    const int jcol = j0 + f4 * 4;
    const bool iok = (icol < N);
    const bool jok2 = (jcol < N);

    float4 pa0, pa1, pb0, pb1;

#define LOADK(k0) {                                                          \
        pa0 = pa1 = pb0 = pb1 = make_float4(0.f, 0.f, 0.f, 0.f);             \
        if (iok) {                                                           \
            pa0 = *reinterpret_cast<const float4*>(&X[(size_t)((k0) + kk0) * N + icol]); \
            pa1 = *reinterpret_cast<const float4*>(&X[(size_t)((k0) + kk1) * N + icol]); \
        }                                                                    \
        if (jok2) {                                                          \
            pb0 = *reinterpret_cast<const float4*>(&X[(size_t)((k0) + kk0) * N + jcol]); \
            pb1 = *reinterpret_cast<const float4*>(&X[(size_t)((k0) + kk1) * N + jcol]); \
        }                                                                    \
    }

    float acc[8][8];
#pragma unroll
    for (int r = 0; r < 8; r++)
#pragma unroll
        for (int c = 0; c < 8; c++) acc[r][c] = 0.f;

    LOADK(0);

#pragma unroll 2
    for (int kt = 0; kt < C / KT; kt++) {
        const int buf = kt & 1;
        *reinterpret_cast<float4*>(&As[buf][kk0][f4 * 4]) = pa0;
        *reinterpret_cast<float4*>(&As[buf][kk1][f4 * 4]) = pa1;
        *reinterpret_cast<float4*>(&Bs[buf][kk0][f4 * 4]) = pb0;
        *reinterpret_cast<float4*>(&Bs[buf][kk1][f4 * 4]) = pb1;
        __syncthreads();
        if (kt + 1 < C / KT) LOADK((kt + 1) * KT);
#pragma unroll
        for (int kk = 0; kk < KT; kk++) {
            float a[8], bb[8];
            *reinterpret_cast<float4*>(&a[0])  = *reinterpret_cast<float4*>(&As[buf][kk][ty * 8]);
            *reinterpret_cast<float4*>(&a[4])  = *reinterpret_cast<float4*>(&As[buf][kk][ty * 8 + 4]);
            *reinterpret_cast<float4*>(&bb[0]) = *reinterpret_cast<float4*>(&Bs[buf][kk][tx * 8]);
            *reinterpret_cast<float4*>(&bb[4]) = *reinterpret_cast<float4*>(&Bs[buf][kk][tx * 8 + 4]);
#pragma unroll
            for (int r = 0; r < 8; r++)
#pragma unroll
                for (int c = 0; c < 8; c++)
                    acc[r][c] = fmaf(a[r], bb[c], acc[r][c]);
        }
    }
#undef LOADK

    __syncthreads();

    // epilogue: acc <- d2 = max(sq_i + sq_j - 2*acc, 0); write + per-batch max
    float sqi[8], sqj[8];
    const int jb = j0 + tx * 8;
    const bool jwr = (jb < N);
#pragma unroll
    for (int r = 0; r < 8; r++) {
        int gi = i0 + ty * 8 + r;
        sqi[r] = (gi < N) ? g_sq[b * N + gi] : 0.f;
    }
#pragma unroll
    for (int c = 0; c < 8; c++) {
        int gj = jb + c;
        sqj[c] = (gj < N) ? g_sq[b * N + gj] : 0.f;
    }
    float tmax = 0.f;
#pragma unroll
    for (int r = 0; r < 8; r++) {
#pragma unroll
        for (int c = 0; c < 8; c++)
            acc[r][c] = fmaxf(sqi[r] + sqj[c] - 2.f * acc[r][c], 0.f);
        int gi = i0 + ty * 8 + r;
        if (gi < N && jwr) {
#pragma unroll
            for (int c = 0; c < 8; c++) tmax = fmaxf(tmax, acc[r][c]);
            float* dst = &g_d2[((size_t)b * N + gi) * N + jb];
            *reinterpret_cast<float4*>(dst)     = *reinterpret_cast<float4*>(&acc[r][0]);
            *reinterpret_cast<float4*>(dst + 4) = *reinterpret_cast<float4*>(&acc[r][4]);
        }
    }

    // block max -> one atomic per block
    red[tid] = tmax;
    __syncthreads();
    for (int o = 128; o > 0; o >>= 1) {
        if (tid < o) red[tid] = fmaxf(red[tid], red[tid + o]);
        __syncthreads();
    }
    if (tid == 0) atomicMax(&g_maxb[b], __float_as_uint(red[0]));

    // mirror write for off-diagonal tiles (coalesced via smem transpose)
    if (ti != tj) {
        for (int s = 0; s < 8; s++) {   // 8 chunks of 16 j-rows
            __syncthreads();
            if ((tx >> 1) == s) {
#pragma unroll
                for (int c = 0; c < 8; c++)
#pragma unroll
                    for (int r = 0; r < 8; r++)
                        Ts[(tx & 1) * 8 + c][ty * 8 + r] = acc[r][c];
            }
            __syncthreads();
#pragma unroll
            for (int w = 0; w < 2; w++) {
                int slot = tid + 256 * w;     // 512 float4 slots = 16 rows x 32 float4
                int jr = slot >> 5;
                int q4 = slot & 31;
                int gj = j0 + s * 16 + jr;
                int gi = i0 + q4 * 4;
                if (gj < N && gi < N) {
                    float4 v = make_float4(Ts[jr][q4 * 4], Ts[jr][q4 * 4 + 1],
                                           Ts[jr][q4 * 4 + 2], Ts[jr][q4 * 4 + 3]);
                    *reinterpret_cast<float4*>(&g_d2[((size_t)b * N + gj) * N + gi]) = v;
                }
            }
        }
    }
}

// branchless sorted-5 insert: 9 FMNMX, keeps b0<=b1<=b2<=b3<=b4 = 5 smallest
#define INS5(v) {                                   \
        float w_ = (v), t_;                         \
        t_ = fminf(b0, w_); w_ = fmaxf(b0, w_); b0 = t_; \
        t_ = fminf(b1, w_); w_ = fmaxf(b1, w_); b1 = t_; \
        t_ = fminf(b2, w_); w_ = fmaxf(b2, w_); b2 = t_; \
        t_ = fminf(b3, w_); w_ = fmaxf(b3, w_); b3 = t_; \
        b4 = fminf(b4, w_);                         \
    }

// 5-NN density + threefry noise — one WARP per row, branchless insert
__global__ void knn_kernel() {
    int w = (blockIdx.x * blockDim.x + threadIdx.x) >> 5;
    int lane = threadIdx.x & 31;
    if (w >= B * N) return;
    const float4* row = reinterpret_cast<const float4*>(&g_d2[(size_t)w * N]);
    float b0 = 3.4e38f, b1 = 3.4e38f, b2 = 3.4e38f, b3 = 3.4e38f, b4 = 3.4e38f;
#pragma unroll 4
    for (int q = lane; q < NQ; q += 32) {
        float4 v = row[q];
        INS5(v.x); INS5(v.y); INS5(v.z); INS5(v.w);
    }
    // warp merge: consume 5 global minima in ascending order (same sum order as scalar)
    float s = 0.f;
#pragma unroll
    for (int t = 0; t < 5; t++) {
        float m = b0;
#pragma unroll
        for (int o = 16; o > 0; o >>= 1) m = fminf(m, __shfl_xor_sync(0xffffffffu, m, o));
        unsigned bal = __ballot_sync(0xffffffffu, b0 == m);
        if (lane == (__ffs(bal) - 1)) {
            b0 = b1; b1 = b2; b2 = b3; b3 = b4; b4 = 3.4e38f;
        }
        float d = sqrtf(m) / 16.0f;
        s = s + d * d;
    }
    if (lane == 0)
        g_dens[w] = expf(-(s / 5.0f)) + jax_uniform_noise(w) * 1e-6f;
}

// dist_parent + score — one WARP per row (coalesced)
__global__ void parent_kernel() {
    int w = (blockIdx.x * blockDim.x + threadIdx.x) >> 5;
    int lane = threadIdx.x & 31;
    if (w >= B * N) return;
    int b = w / N;
    float di = g_dens[w];
    const float4* row = reinterpret_cast<const float4*>(&g_d2[(size_t)w * N]);
    const float4* dr  = reinterpret_cast<const float4*>(&g_dens[(size_t)b * N]);
    float mn = 3.4e38f;
#pragma unroll 4
    for (int q = lane; q < NQ; q += 32) {
        float4 v = row[q];
        float4 dd = dr[q];
        if (dd.x > di) mn = fminf(mn, v.x);
        if (dd.y > di) mn = fminf(mn, v.y);
        if (dd.z > di) mn = fminf(mn, v.z);
        if (dd.w > di) mn = fminf(mn, v.w);
    }
#pragma unroll
    for (int o = 16; o > 0; o >>= 1) mn = fminf(mn, __shfl_xor_sync(0xffffffffu, mn, o));
    if (lane == 0) {
        float dmax = sqrtf(__uint_as_float(g_maxb[b])) / 16.0f;
        float dp = fminf(dmax, sqrtf(mn) / 16.0f);
        g_score[w] = dp * di;
    }
}

// per-batch top-50, jax top_k tie-break (lower index wins on equal score)
__global__ void topk_kernel() {
    int b = blockIdx.x;
    __shared__ float s[N];
    __shared__ float rs[256];
    __shared__ int   ri[256];
    int t = threadIdx.x;
    for (int i = t; i < N; i += 256) s[i] = g_score[b * N + i];
    __syncthreads();
    for (int m = 0; m < NC; m++) {
        float bs = -3.4e38f;
        int   bi = N;
        for (int i = t; i < N; i += 256) {
            float v = s[i];
            if (v > bs || (v == bs && i < bi)) { bs = v; bi = i; }
        }
        rs[t] = bs; ri[t] = bi;
        __syncthreads();
        for (int o = 128; o > 0; o >>= 1) {
            if (t < o) {
                if (rs[t + o] > rs[t] || (rs[t + o] == rs[t] && ri[t + o] < ri[t])) {
                    rs[t] = rs[t + o]; ri[t] = ri[t + o];
                }
            }
            __syncthreads();
        }
        if (t == 0) {
            g_idx[b * NC + m] = ri[0];
            s[ri[0]] = -3.4e38f;
        }
        __syncthreads();
    }
}

__global__ void gather_kernel(const float* __restrict__ x, float* __restrict__ out) {
    int g = blockIdx.x * blockDim.x + threadIdx.x;
    if (g >= B * C * NC) return;
    int m = g % NC;
    int c = (g / NC) % C;
    int b = g / (NC * C);
    int idx = g_idx[b * NC + m];
    out[g] = x[(size_t)b * C * N + (size_t)c * N + idx];
}

// ---------------- launch -----------------------------------------------------
extern "C" void kernel_launch(void* const* d_in, const int* in_sizes, int n_in,
                              void* d_out, int out_size) {
    const float* x = (const float*)d_in[0];
    float* out = (float*)d_out;

    init_kernel<<<1, 32>>>();
    sq_kernel<<<(B * N + 255) / 256, 256>>>(x);
    dim3 gg(NPAIRS, 1, B);
    gram_kernel<<<gg, 256>>>(x);
    int rows = B * N;                        // one warp per row
    knn_kernel<<<(rows * 32 + 255) / 256, 256>>>();
    parent_kernel<<<(rows * 32 + 255) / 256, 256>>>();
    topk_kernel<<<B, 256>>>();
    gather_kernel<<<(B * C * NC + 255) / 256, 256>>>(x, out);
}

// round 4
// speedup vs baseline: 2.1708x; 1.0253x over previous
#include <cuda_runtime.h>
#include <cstdint>

#define B 8
#define C 256
#define N 3136
#define NQ (N/4)
#define NC 50
#define TILE 128
#define KT 16
#define NT 25              // ceil(N/128)
#define NPAIRS (NT*(NT+1)/2)   // 325 upper-triangle tile pairs

// ---------------- scratch (static device globals: allocation-guard safe) ----
__device__ float    g_d2[(size_t)B * N * N];   // clamped squared distances (raw, before /C)
__device__ float    g_sq[B * N];
__device__ float    g_dens[B * N];
__device__ float    g_score[B * N];
__device__ unsigned g_maxb[B];
__device__ int      g_idx[B * NC];

// ---------------- threefry-2x32 (JAX-compatible) ---------------------------
__device__ __forceinline__ uint32_t rotl32(uint32_t x, int r) {
    return (x << r) | (x >> (32 - r));
}

__device__ __forceinline__ void threefry2x32_k42(uint32_t x0, uint32_t x1,
                                                 uint32_t& o0, uint32_t& o1) {
    const uint32_t ks0 = 0u;
    const uint32_t ks1 = 42u;
    const uint32_t ks2 = 0x1BD11BDAu ^ 42u;
    x0 += ks0; x1 += ks1;
#define TF_RND(r) { x0 += x1; x1 = rotl32(x1, r); x1 ^= x0; }
    TF_RND(13) TF_RND(15) TF_RND(26) TF_RND(6)
    x0 += ks1; x1 += ks2 + 1u;
    TF_RND(17) TF_RND(29) TF_RND(16) TF_RND(24)
    x0 += ks2; x1 += ks0 + 2u;
    TF_RND(13) TF_RND(15) TF_RND(26) TF_RND(6)
    x0 += ks0; x1 += ks1 + 3u;
    TF_RND(17) TF_RND(29) TF_RND(16) TF_RND(24)
    x0 += ks1; x1 += ks2 + 4u;
    TF_RND(13) TF_RND(15) TF_RND(26) TF_RND(6)
    x0 += ks2; x1 += ks0 + 5u;
#undef TF_RND
    o0 = x0; o1 = x1;
}

__device__ __forceinline__ float jax_uniform_noise(int g) {
    const int half = (B * N) / 2;  // 12544
    uint32_t lane = (g < half) ? (uint32_t)g : (uint32_t)(g - half);
    uint32_t o0, o1;
    threefry2x32_k42(lane, lane + (uint32_t)half, o0, o1);
    uint32_t bits = (g < half) ? o0 : o1;
    return __uint_as_float((bits >> 9) | 0x3F800000u) - 1.0f;
}

// packed fp32x2 FMA (Blackwell): each half is a bit-exact IEEE fp32 FMA
__device__ __forceinline__ unsigned long long ffma2(unsigned long long a,
                                                    unsigned long long b,
                                                    unsigned long long c) {
    unsigned long long d;
    asm("fma.rn.f32x2 %0, %1, %2, %3;" : "=l"(d) : "l"(a), "l"(b), "l"(c));
    return d;
}

__device__ __forceinline__ unsigned long long dup2(float a) {
    unsigned long long d;
    asm("mov.b64 %0, {%1, %1};" : "=l"(d) : "f"(a));
    return d;
}

// ---------------- kernels ---------------------------------------------------
__global__ void init_kernel() {
    int t = threadIdx.x;
    if (t < B) g_maxb[t] = 0u;
}

__global__ void sq_kernel(const float* __restrict__ x) {
    int g = blockIdx.x * blockDim.x + threadIdx.x;
    if (g >= B * N) return;
    int b = g / N, n = g % N;
    const float* p = x + (size_t)b * C * N + n;
    float s = 0.f;
#pragma unroll 8
    for (int c = 0; c < C; c++) {
        float v = p[(size_t)c * N];
        s = fmaf(v, v, s);
    }
    g_sq[g] = s;
}

// Symmetric Gram: upper-triangle 128x128 tile pairs; double-buffered mainloop;
// packed f32x2 FMA inner loop; mirror-write via smem transpose.
__global__ __launch_bounds__(256, 2) void gram_kernel(const float* __restrict__ x) {
    const int b = blockIdx.z;

    // decode upper-triangle pair index -> (ti, tj), tj >= ti
    int rem = blockIdx.x;
    int ti = 0;
    while (rem >= NT - ti) { rem -= NT - ti; ti++; }
    const int tj = ti + rem;
    const int i0 = ti * TILE;
    const int j0 = tj * TILE;

    const float* X = x + (size_t)b * C * N;

    __shared__ float As[2][KT][TILE];
    __shared__ float Bs[2][KT][TILE];
    __shared__ float Ts[16][129];      // transpose staging (padded)
    __shared__ float red[256];

    const int tid = threadIdx.x;
    const int tx = tid & 15;   // 16 threads over j
    const int ty = tid >> 4;   // 16 threads over i

    // per-thread load slots (2 float4 per array per K-step)
    const int kk0 = tid >> 5;            // slot s=0
    const int kk1 = (tid + 256) >> 5;    // slot s=1
    const int f4  = tid & 31;
    const int icol = i0 + f4 * 4;
    const int jcol = j0 + f4 * 4;
    const bool iok = (icol < N);
    const bool jok2 = (jcol < N);

    float4 pa0, pa1, pb0, pb1;

#define LOADK(k0) {                                                          \
        pa0 = pa1 = pb0 = pb1 = make_float4(0.f, 0.f, 0.f, 0.f);             \
        if (iok) {                                                           \
            pa0 = *reinterpret_cast<const float4*>(&X[(size_t)((k0) + kk0) * N + icol]); \
            pa1 = *reinterpret_cast<const float4*>(&X[(size_t)((k0) + kk1) * N + icol]); \
        }                                                                    \
        if (jok2) {                                                          \
            pb0 = *reinterpret_cast<const float4*>(&X[(size_t)((k0) + kk0) * N + jcol]); \
            pb1 = *reinterpret_cast<const float4*>(&X[(size_t)((k0) + kk1) * N + jcol]); \
        }                                                                    \
    }

    // packed accumulators: acc2[r][c2] holds cols (2*c2, 2*c2+1)
    unsigned long long acc2[8][4];
#pragma unroll
    for (int r = 0; r < 8; r++)
#pragma unroll
        for (int c = 0; c < 4; c++) acc2[r][c] = 0ull;

    LOADK(0);

#pragma unroll 2
    for (int kt = 0; kt < C / KT; kt++) {
        const int buf = kt & 1;
        *reinterpret_cast<float4*>(&As[buf][kk0][f4 * 4]) = pa0;
        *reinterpret_cast<float4*>(&As[buf][kk1][f4 * 4]) = pa1;
        *reinterpret_cast<float4*>(&Bs[buf][kk0][f4 * 4]) = pb0;
        *reinterpret_cast<float4*>(&Bs[buf][kk1][f4 * 4]) = pb1;
        __syncthreads();
        if (kt + 1 < C / KT) LOADK((kt + 1) * KT);
#pragma unroll
        for (int kk = 0; kk < KT; kk++) {
            float a[8];
            *reinterpret_cast<float4*>(&a[0]) = *reinterpret_cast<float4*>(&As[buf][kk][ty * 8]);
            *reinterpret_cast<float4*>(&a[4]) = *reinterpret_cast<float4*>(&As[buf][kk][ty * 8 + 4]);
            ulonglong2 bp0 = *reinterpret_cast<ulonglong2*>(&Bs[buf][kk][tx * 8]);
            ulonglong2 bp1 = *reinterpret_cast<ulonglong2*>(&Bs[buf][kk][tx * 8 + 4]);
#pragma unroll
            for (int r = 0; r < 8; r++) {
                unsigned long long ad = dup2(a[r]);
                acc2[r][0] = ffma2(ad, bp0.x, acc2[r][0]);
                acc2[r][1] = ffma2(ad, bp0.y, acc2[r][1]);
                acc2[r][2] = ffma2(ad, bp1.x, acc2[r][2]);
                acc2[r][3] = ffma2(ad, bp1.y, acc2[r][3]);
            }
        }
    }
#undef LOADK

    __syncthreads();

    // unpack accumulators (each half is bitwise identical to the scalar version)
    float acc[8][8];
#pragma unroll
    for (int r = 0; r < 8; r++)
#pragma unroll
        for (int c = 0; c < 4; c++) {
            unsigned long long v = acc2[r][c];
            acc[r][2 * c]     = __uint_as_float((uint32_t)(v & 0xffffffffu));
            acc[r][2 * c + 1] = __uint_as_float((uint32_t)(v >> 32));
        }

    // epilogue: acc <- d2 = max(sq_i + sq_j - 2*acc, 0); write + per-batch max
    float sqi[8], sqj[8];
    const int jb = j0 + tx * 8;
    const bool jwr = (jb < N);
#pragma unroll
    for (int r = 0; r < 8; r++) {
        int gi = i0 + ty * 8 + r;
        sqi[r] = (gi < N) ? g_sq[b * N + gi] : 0.f;
    }
#pragma unroll
    for (int c = 0; c < 8; c++) {
        int gj = jb + c;
        sqj[c] = (gj < N) ? g_sq[b * N + gj] : 0.f;
    }
    float tmax = 0.f;
#pragma unroll
    for (int r = 0; r < 8; r++) {
#pragma unroll
        for (int c = 0; c < 8; c++)
            acc[r][c] = fmaxf(sqi[r] + sqj[c] - 2.f * acc[r][c], 0.f);
        int gi = i0 + ty * 8 + r;
        if (gi < N && jwr) {
#pragma unroll
            for (int c = 0; c < 8; c++) tmax = fmaxf(tmax, acc[r][c]);
            float* dst = &g_d2[((size_t)b * N + gi) * N + jb];
            *reinterpret_cast<float4*>(dst)     = *reinterpret_cast<float4*>(&acc[r][0]);
            *reinterpret_cast<float4*>(dst + 4) = *reinterpret_cast<float4*>(&acc[r][4]);
        }
    }

    // block max -> one atomic per block
    red[tid] = tmax;
    __syncthreads();
    for (int o = 128; o > 0; o >>= 1) {
        if (tid < o) red[tid] = fmaxf(red[tid], red[tid + o]);
        __syncthreads();
    }
    if (tid == 0) atomicMax(&g_maxb[b], __float_as_uint(red[0]));

    // mirror write for off-diagonal tiles (coalesced via smem transpose)
    if (ti != tj) {
        for (int s = 0; s < 8; s++) {   // 8 chunks of 16 j-rows
            __syncthreads();
            if ((tx >> 1) == s) {
#pragma unroll
                for (int c = 0; c < 8; c++)
#pragma unroll
                    for (int r = 0; r < 8; r++)
                        Ts[(tx & 1) * 8 + c][ty * 8 + r] = acc[r][c];
            }
            __syncthreads();
#pragma unroll
            for (int w = 0; w < 2; w++) {
                int slot = tid + 256 * w;     // 512 float4 slots = 16 rows x 32 float4
                int jr = slot >> 5;
                int q4 = slot & 31;
                int gj = j0 + s * 16 + jr;
                int gi = i0 + q4 * 4;
                if (gj < N && gi < N) {
                    float4 v = make_float4(Ts[jr][q4 * 4], Ts[jr][q4 * 4 + 1],
                                           Ts[jr][q4 * 4 + 2], Ts[jr][q4 * 4 + 3]);
                    *reinterpret_cast<float4*>(&g_d2[((size_t)b * N + gj) * N + gi]) = v;
                }
            }
        }
    }
}

// branchless sorted-5 insert: 9 FMNMX, keeps b0<=b1<=b2<=b3<=b4 = 5 smallest
#define INS5(v) {                                   \
        float w_ = (v), t_;                         \
        t_ = fminf(b0, w_); w_ = fmaxf(b0, w_); b0 = t_; \
        t_ = fminf(b1, w_); w_ = fmaxf(b1, w_); b1 = t_; \
        t_ = fminf(b2, w_); w_ = fmaxf(b2, w_); b2 = t_; \
        t_ = fminf(b3, w_); w_ = fmaxf(b3, w_); b3 = t_; \
        b4 = fminf(b4, w_);                         \
    }

// 5-NN density + threefry noise — one WARP per row, branchless insert
__global__ void knn_kernel() {
    int w = (blockIdx.x * blockDim.x + threadIdx.x) >> 5;
    int lane = threadIdx.x & 31;
    if (w >= B * N) return;
    const float4* row = reinterpret_cast<const float4*>(&g_d2[(size_t)w * N]);
    float b0 = 3.4e38f, b1 = 3.4e38f, b2 = 3.4e38f, b3 = 3.4e38f, b4 = 3.4e38f;
#pragma unroll 4
    for (int q = lane; q < NQ; q += 32) {
        float4 v = row[q];
        INS5(v.x); INS5(v.y); INS5(v.z); INS5(v.w);
    }
    // warp merge: consume 5 global minima in ascending order (same sum order as scalar)
    float s = 0.f;
#pragma unroll
    for (int t = 0; t < 5; t++) {
        float m = b0;
#pragma unroll
        for (int o = 16; o > 0; o >>= 1) m = fminf(m, __shfl_xor_sync(0xffffffffu, m, o));
        unsigned bal = __ballot_sync(0xffffffffu, b0 == m);
        if (lane == (__ffs(bal) - 1)) {
            b0 = b1; b1 = b2; b2 = b3; b3 = b4; b4 = 3.4e38f;
        }
        float d = sqrtf(m) / 16.0f;
        s = s + d * d;
    }
    if (lane == 0)
        g_dens[w] = expf(-(s / 5.0f)) + jax_uniform_noise(w) * 1e-6f;
}

// dist_parent + score — one WARP per row (coalesced)
__global__ void parent_kernel() {
    int w = (blockIdx.x * blockDim.x + threadIdx.x) >> 5;
    int lane = threadIdx.x & 31;
    if (w >= B * N) return;
    int b = w / N;
    float di = g_dens[w];
    const float4* row = reinterpret_cast<const float4*>(&g_d2[(size_t)w * N]);
    const float4* dr  = reinterpret_cast<const float4*>(&g_dens[(size_t)b * N]);
    float mn = 3.4e38f;
#pragma unroll 4
    for (int q = lane; q < NQ; q += 32) {
        float4 v = row[q];
        float4 dd = dr[q];
        if (dd.x > di) mn = fminf(mn, v.x);
        if (dd.y > di) mn = fminf(mn, v.y);
        if (dd.z > di) mn = fminf(mn, v.z);
        if (dd.w > di) mn = fminf(mn, v.w);
    }
#pragma unroll
    for (int o = 16; o > 0; o >>= 1) mn = fminf(mn, __shfl_xor_sync(0xffffffffu, mn, o));
    if (lane == 0) {
        float dmax = sqrtf(__uint_as_float(g_maxb[b])) / 16.0f;
        float dp = fminf(dmax, sqrtf(mn) / 16.0f);
        g_score[w] = dp * di;
    }
}

// per-batch top-50, jax top_k tie-break (lower index wins on equal score)
__global__ void topk_kernel() {
    int b = blockIdx.x;
    __shared__ float s[N];
    __shared__ float rs[256];
    __shared__ int   ri[256];
    int t = threadIdx.x;
    for (int i = t; i < N; i += 256) s[i] = g_score[b * N + i];
    __syncthreads();
    for (int m = 0; m < NC; m++) {
        float bs = -3.4e38f;
        int   bi = N;
        for (int i = t; i < N; i += 256) {
            float v = s[i];
            if (v > bs || (v == bs && i < bi)) { bs = v; bi = i; }
        }
        rs[t] = bs; ri[t] = bi;
        __syncthreads();
        for (int o = 128; o > 0; o >>= 1) {
            if (t < o) {
                if (rs[t + o] > rs[t] || (rs[t + o] == rs[t] && ri[t + o] < ri[t])) {
                    rs[t] = rs[t + o]; ri[t] = ri[t + o];
                }
            }
            __syncthreads();
        }
        if (t == 0) {
            g_idx[b * NC + m] = ri[0];
            s[ri[0]] = -3.4e38f;
        }
        __syncthreads();
    }
}

__global__ void gather_kernel(const float* __restrict__ x, float* __restrict__ out) {
    int g = blockIdx.x * blockDim.x + threadIdx.x;
    if (g >= B * C * NC) return;
    int m = g % NC;
    int c = (g / NC) % C;
    int b = g / (NC * C);
    int idx = g_idx[b * NC + m];
    out[g] = x[(size_t)b * C * N + (size_t)c * N + idx];
}

// ---------------- launch -----------------------------------------------------
extern "C" void kernel_launch(void* const* d_in, const int* in_sizes, int n_in,
                              void* d_out, int out_size) {
    const float* x = (const float*)d_in[0];
    float* out = (float*)d_out;

    init_kernel<<<1, 32>>>();
    sq_kernel<<<(B * N + 255) / 256, 256>>>(x);
    dim3 gg(NPAIRS, 1, B);
    gram_kernel<<<gg, 256>>>(x);
    int rows = B * N;                        // one warp per row
    knn_kernel<<<(rows * 32 + 255) / 256, 256>>>();
    parent_kernel<<<(rows * 32 + 255) / 256, 256>>>();
    topk_kernel<<<B, 256>>>();
    gather_kernel<<<(B * C * NC + 255) / 256, 256>>>(x, out);
}